// round 1
// baseline (speedup 1.0000x reference)
#include <cuda_runtime.h>

// ---------------------------------------------------------------------------
// HybridModel: conv1(3->16)+bn+relu+pool -> conv2(16->32)+... -> conv3(32->64)+...
// -> per-block proj (16 blocks x 256 -> 8) -> theta=0.5*tanh(z)
// -> quantum features (analytic: products of cos(theta)) -> classifier (10)
// Batch = 512, input (512,3,64,64), output (512,10) float32.
// ---------------------------------------------------------------------------

__device__ float g_h1[512 * 16 * 32 * 32];   // 33.5 MB
__device__ float g_h2[512 * 32 * 16 * 16];   // 16.8 MB
__device__ float g_h3[512 * 64 * 8 * 8];     //  8.4 MB

// ---------------------------------------------------------------------------
// conv1: in (b,3,64,64) -> fused bn/relu/pool -> (b,16,32,32)
// grid (2,2,512), 256 threads = 16x16 pooled tile
// ---------------------------------------------------------------------------
__global__ __launch_bounds__(256) void conv1_kernel(
    const float* __restrict__ x, const float* __restrict__ w,
    const float* __restrict__ cb, const float* __restrict__ bg,
    const float* __restrict__ bb, const float* __restrict__ bm,
    const float* __restrict__ bv)
{
    __shared__ float sp[3][34][34];
    __shared__ float swt[3][9][16];
    __shared__ float ssc[16], ssh[16];

    int b = blockIdx.z, ty = blockIdx.y, tx = blockIdx.x;
    int tid = threadIdx.x;

    // weights (16,3,3,3) -> swt[ic][k][oc]
    for (int i = tid; i < 16 * 27; i += 256) {
        int oc = i / 27, r = i % 27, ic = r / 9, k = r % 9;
        swt[ic][k][oc] = w[i];
    }
    if (tid < 16) {
        float inv = bg[tid] * rsqrtf(bv[tid] + 1e-5f);
        ssc[tid] = inv;
        ssh[tid] = (cb[tid] - bm[tid]) * inv + bb[tid];
    }
    int y0 = ty * 32 - 1, x0 = tx * 32 - 1;
    const float* xb = x + b * 3 * 64 * 64;
    for (int i = tid; i < 3 * 34 * 34; i += 256) {
        int ic = i / 1156, r = i % 1156, yy = r / 34, xx = r % 34;
        int gy = y0 + yy, gx = x0 + xx;
        float val = 0.f;
        if ((unsigned)gy < 64u && (unsigned)gx < 64u)
            val = xb[(ic * 64 + gy) * 64 + gx];
        sp[ic][yy][xx] = val;
    }
    __syncthreads();

    int py = tid >> 4, px = tid & 15;
    int by = 2 * py, bx = 2 * px;

    float acc[4][16];
#pragma unroll
    for (int p = 0; p < 4; p++)
#pragma unroll
        for (int oc = 0; oc < 16; oc++) acc[p][oc] = 0.f;

#pragma unroll 1
    for (int ic = 0; ic < 3; ic++) {
        float vv[4][4];
#pragma unroll
        for (int a = 0; a < 4; a++)
#pragma unroll
            for (int c = 0; c < 4; c++) vv[a][c] = sp[ic][by + a][bx + c];
#pragma unroll
        for (int oc = 0; oc < 16; oc++) {
#pragma unroll
            for (int k = 0; k < 9; k++) {
                const int ky = k / 3, kx = k % 3;
                float wv = swt[ic][k][oc];
                acc[0][oc] += vv[ky][kx] * wv;
                acc[1][oc] += vv[ky][kx + 1] * wv;
                acc[2][oc] += vv[ky + 1][kx] * wv;
                acc[3][oc] += vv[ky + 1][kx + 1] * wv;
            }
        }
    }

    int gpy = ty * 16 + py, gpx = tx * 16 + px;
    float* o = g_h1 + ((size_t)b * 16 * 32 + gpy) * 32 + gpx;
#pragma unroll
    for (int oc = 0; oc < 16; oc++) {
        float sc = ssc[oc], sh = ssh[oc];
        float v0 = fmaxf(acc[0][oc] * sc + sh, 0.f);
        float v1 = fmaxf(acc[1][oc] * sc + sh, 0.f);
        float v2 = fmaxf(acc[2][oc] * sc + sh, 0.f);
        float v3 = fmaxf(acc[3][oc] * sc + sh, 0.f);
        o[(size_t)oc * 32 * 32] = fmaxf(fmaxf(v0, v1), fmaxf(v2, v3));
    }
}

// ---------------------------------------------------------------------------
// conv2: (b,16,32,32) -> (b,32,16,16). grid (2,2,512), 256 threads:
// 64 pooled pixels (8x8 tile) x 4 oc-groups of 8 channels.
// ---------------------------------------------------------------------------
__global__ __launch_bounds__(256) void conv2_kernel(
    const float* __restrict__ w, const float* __restrict__ cb,
    const float* __restrict__ bg, const float* __restrict__ bb,
    const float* __restrict__ bm, const float* __restrict__ bv)
{
    __shared__ float sp[16][18][18];
    __shared__ float swt[16][9][32];
    __shared__ float ssc[32], ssh[32];

    int b = blockIdx.z, ty = blockIdx.y, tx = blockIdx.x;
    int tid = threadIdx.x;

    // weights (32,16,3,3) -> swt[ic][k][oc]
    for (int i = tid; i < 32 * 144; i += 256) {
        int oc = i / 144, r = i % 144, ic = r / 9, k = r % 9;
        swt[ic][k][oc] = w[i];
    }
    if (tid < 32) {
        float inv = bg[tid] * rsqrtf(bv[tid] + 1e-5f);
        ssc[tid] = inv;
        ssh[tid] = (cb[tid] - bm[tid]) * inv + bb[tid];
    }
    int y0 = ty * 16 - 1, x0 = tx * 16 - 1;
    const float* ib = g_h1 + (size_t)b * 16 * 32 * 32;
    for (int i = tid; i < 16 * 324; i += 256) {
        int ic = i / 324, r = i % 324, yy = r / 18, xx = r % 18;
        int gy = y0 + yy, gx = x0 + xx;
        float val = 0.f;
        if ((unsigned)gy < 32u && (unsigned)gx < 32u)
            val = ib[(ic * 32 + gy) * 32 + gx];
        sp[ic][yy][xx] = val;
    }
    __syncthreads();

    int pix = tid & 63, ocg = tid >> 6;
    int py = pix >> 3, px = pix & 7;
    int by = 2 * py, bx = 2 * px;
    int oc0 = ocg * 8;

    float acc[4][8];
#pragma unroll
    for (int p = 0; p < 4; p++)
#pragma unroll
        for (int oc = 0; oc < 8; oc++) acc[p][oc] = 0.f;

#pragma unroll 1
    for (int ic = 0; ic < 16; ic++) {
        float vv[4][4];
#pragma unroll
        for (int a = 0; a < 4; a++)
#pragma unroll
            for (int c = 0; c < 4; c++) vv[a][c] = sp[ic][by + a][bx + c];
#pragma unroll
        for (int oc = 0; oc < 8; oc++) {
#pragma unroll
            for (int k = 0; k < 9; k++) {
                const int ky = k / 3, kx = k % 3;
                float wv = swt[ic][k][oc0 + oc];
                acc[0][oc] += vv[ky][kx] * wv;
                acc[1][oc] += vv[ky][kx + 1] * wv;
                acc[2][oc] += vv[ky + 1][kx] * wv;
                acc[3][oc] += vv[ky + 1][kx + 1] * wv;
            }
        }
    }

    int gpy = ty * 8 + py, gpx = tx * 8 + px;
#pragma unroll
    for (int oc = 0; oc < 8; oc++) {
        int c = oc0 + oc;
        float sc = ssc[c], sh = ssh[c];
        float v0 = fmaxf(acc[0][oc] * sc + sh, 0.f);
        float v1 = fmaxf(acc[1][oc] * sc + sh, 0.f);
        float v2 = fmaxf(acc[2][oc] * sc + sh, 0.f);
        float v3 = fmaxf(acc[3][oc] * sc + sh, 0.f);
        g_h2[(((size_t)b * 32 + c) * 16 + gpy) * 16 + gpx] =
            fmaxf(fmaxf(v0, v1), fmaxf(v2, v3));
    }
}

// ---------------------------------------------------------------------------
// conv3: (b,32,16,16) -> (b,64,8,8). One block per image, 512 threads:
// 64 pooled pixels x 8 oc-groups of 8 channels. 4 input-channel chunks of 8.
// ---------------------------------------------------------------------------
__global__ __launch_bounds__(512) void conv3_kernel(
    const float* __restrict__ w, const float* __restrict__ cb,
    const float* __restrict__ bg, const float* __restrict__ bb,
    const float* __restrict__ bm, const float* __restrict__ bv)
{
    __shared__ float sp[8][18][18];
    __shared__ float swt[8][9][64];
    __shared__ float ssc[64], ssh[64];

    int b = blockIdx.x;
    int tid = threadIdx.x;

    if (tid < 64) {
        float inv = bg[tid] * rsqrtf(bv[tid] + 1e-5f);
        ssc[tid] = inv;
        ssh[tid] = (cb[tid] - bm[tid]) * inv + bb[tid];
    }

    int pix = tid & 63, ocg = tid >> 6;
    int py = pix >> 3, px = pix & 7;
    int by = 2 * py, bx = 2 * px;
    int oc0 = ocg * 8;
    const float* ib = g_h2 + (size_t)b * 32 * 16 * 16;

    float acc[4][8];
#pragma unroll
    for (int p = 0; p < 4; p++)
#pragma unroll
        for (int oc = 0; oc < 8; oc++) acc[p][oc] = 0.f;

#pragma unroll 1
    for (int ch = 0; ch < 4; ch++) {
        __syncthreads();
        for (int i = tid; i < 8 * 324; i += 512) {
            int ic = i / 324, r = i % 324, yy = r / 18, xx = r % 18;
            int gy = yy - 1, gx = xx - 1;
            float val = 0.f;
            if ((unsigned)gy < 16u && (unsigned)gx < 16u)
                val = ib[((ch * 8 + ic) * 16 + gy) * 16 + gx];
            sp[ic][yy][xx] = val;
        }
        // weights (64,32,3,3)
        for (int i = tid; i < 64 * 72; i += 512) {
            int oc = i / 72, r = i % 72, ic = r / 9, k = r % 9;
            swt[ic][k][oc] = w[(oc * 32 + ch * 8 + ic) * 9 + k];
        }
        __syncthreads();

#pragma unroll 1
        for (int ic = 0; ic < 8; ic++) {
            float vv[4][4];
#pragma unroll
            for (int a = 0; a < 4; a++)
#pragma unroll
                for (int c = 0; c < 4; c++) vv[a][c] = sp[ic][by + a][bx + c];
#pragma unroll
            for (int oc = 0; oc < 8; oc++) {
#pragma unroll
                for (int k = 0; k < 9; k++) {
                    const int ky = k / 3, kx = k % 3;
                    float wv = swt[ic][k][oc0 + oc];
                    acc[0][oc] += vv[ky][kx] * wv;
                    acc[1][oc] += vv[ky][kx + 1] * wv;
                    acc[2][oc] += vv[ky + 1][kx] * wv;
                    acc[3][oc] += vv[ky + 1][kx + 1] * wv;
                }
            }
        }
    }

#pragma unroll
    for (int oc = 0; oc < 8; oc++) {
        int c = oc0 + oc;
        float sc = ssc[c], sh = ssh[c];
        float v0 = fmaxf(acc[0][oc] * sc + sh, 0.f);
        float v1 = fmaxf(acc[1][oc] * sc + sh, 0.f);
        float v2 = fmaxf(acc[2][oc] * sc + sh, 0.f);
        float v3 = fmaxf(acc[3][oc] * sc + sh, 0.f);
        g_h3[(size_t)b * 4096 + c * 64 + py * 8 + px] =
            fmaxf(fmaxf(v0, v1), fmaxf(v2, v3));
    }
}

// ---------------------------------------------------------------------------
// head: feats (16,256) -> z (16,8) -> theta=0.5*tanh(z) -> analytic quantum
// features (products of cos(theta)) -> classifier (10).
// One block per batch element, 128 threads.
// ---------------------------------------------------------------------------
__global__ __launch_bounds__(128) void head_kernel(
    const float* __restrict__ pw, const float* __restrict__ pb,
    const float* __restrict__ cw, const float* __restrict__ cbias,
    float* __restrict__ out)
{
    __shared__ float sf[4096];
    __shared__ float spart[128 * 8];
    __shared__ float scos[128];
    __shared__ float sfeat[576];
    __shared__ float scpart[10][8];

    int b = blockIdx.x, tid = threadIdx.x;

    const float4* fp4 = (const float4*)(g_h3 + (size_t)b * 4096);
    float4* sf4 = (float4*)sf;
    for (int i = tid; i < 1024; i += 128) sf4[i] = fp4[i];
    __syncthreads();

    // z partial sums: thread (k, cs); cs covers 32 of the 256 c-values.
    {
        int k = tid >> 3, cs = tid & 7;
        float part[8];
#pragma unroll
        for (int d = 0; d < 8; d++) part[d] = 0.f;
        const float* fr = sf + k * 256 + cs * 32;
        const float* wr = pw + k * 2048 + cs * 32 * 8;
#pragma unroll 4
        for (int c = 0; c < 32; c++) {
            float fv = fr[c];
            float4 w0 = ((const float4*)(wr + c * 8))[0];
            float4 w1 = ((const float4*)(wr + c * 8))[1];
            part[0] += fv * w0.x; part[1] += fv * w0.y;
            part[2] += fv * w0.z; part[3] += fv * w0.w;
            part[4] += fv * w1.x; part[5] += fv * w1.y;
            part[6] += fv * w1.z; part[7] += fv * w1.w;
        }
#pragma unroll
        for (int d = 0; d < 8; d++) spart[tid * 8 + d] = part[d];
    }
    __syncthreads();

    // reduce 8 partials, then cos(0.5*tanh(z))
    {
        int k = tid >> 3, d = tid & 7;
        float z = pb[k * 8 + d];
#pragma unroll
        for (int cs = 0; cs < 8; cs++) z += spart[(k * 8 + cs) * 8 + d];
        scos[tid] = cosf(0.5f * tanhf(z));
    }
    __syncthreads();

    // analytic quantum features per block k:
    // single[q] = prod_{j<=q} cos(theta_j); pair(i,j) = prod_{m=i+1..j} cos(theta_m)
    if (tid < 16) {
        const float* c8 = scos + tid * 8;
        float* fo = sfeat + tid * 36;
        float p = 1.f;
#pragma unroll
        for (int q = 0; q < 8; q++) { p *= c8[q]; fo[q] = p; }
        int idx = 8;
#pragma unroll
        for (int i = 0; i < 8; i++) {
#pragma unroll
            for (int j = i + 1; j < 8; j++) {
                float p2 = 1.f;
                for (int m = i + 1; m <= j; m++) p2 *= c8[m];
                fo[idx++] = p2;
            }
        }
    }
    __syncthreads();

    // classifier: 80 threads compute partials (cls, 72-feature chunk)
    if (tid < 80) {
        int cls = tid >> 3, ch = tid & 7;
        const float* wrow = cw + cls * 576 + ch * 72;
        const float* fr2 = sfeat + ch * 72;
        float s = 0.f;
#pragma unroll 8
        for (int j = 0; j < 72; j++) s += fr2[j] * wrow[j];
        scpart[cls][ch] = s;
    }
    __syncthreads();

    if (tid < 10) {
        float o = cbias[tid];
#pragma unroll
        for (int ch = 0; ch < 8; ch++) o += scpart[tid][ch];
        out[b * 10 + tid] = o;
    }
}

// ---------------------------------------------------------------------------
extern "C" void kernel_launch(void* const* d_in, const int* in_sizes, int n_in,
                              void* d_out, int out_size)
{
    const float* x    = (const float*)d_in[0];
    const float* c1w  = (const float*)d_in[1];
    const float* c1b  = (const float*)d_in[2];
    const float* g1   = (const float*)d_in[3];
    const float* b1   = (const float*)d_in[4];
    const float* m1   = (const float*)d_in[5];
    const float* v1   = (const float*)d_in[6];
    const float* c2w  = (const float*)d_in[7];
    const float* c2b  = (const float*)d_in[8];
    const float* g2   = (const float*)d_in[9];
    const float* b2   = (const float*)d_in[10];
    const float* m2   = (const float*)d_in[11];
    const float* v2   = (const float*)d_in[12];
    const float* c3w  = (const float*)d_in[13];
    const float* c3b  = (const float*)d_in[14];
    const float* g3   = (const float*)d_in[15];
    const float* b3   = (const float*)d_in[16];
    const float* m3   = (const float*)d_in[17];
    const float* v3   = (const float*)d_in[18];
    const float* pw   = (const float*)d_in[19];
    const float* pb   = (const float*)d_in[20];
    const float* cw   = (const float*)d_in[21];
    const float* cb   = (const float*)d_in[22];
    float* out = (float*)d_out;

    conv1_kernel<<<dim3(2, 2, 512), 256>>>(x, c1w, c1b, g1, b1, m1, v1);
    conv2_kernel<<<dim3(2, 2, 512), 256>>>(c2w, c2b, g2, b2, m2, v2);
    conv3_kernel<<<512, 512>>>(c3w, c3b, g3, b3, m3, v3);
    head_kernel<<<512, 128>>>(pw, pb, cw, cb, out);
}

// round 2
// speedup vs baseline: 1.1308x; 1.1308x over previous
#include <cuda_runtime.h>

// ---------------------------------------------------------------------------
// HybridModel, Round 2: packed f32x2 FFMA2 convolutions (2x fp32 FMA rate on
// sm_103a), oc-pair packing. Head unchanged.
// ---------------------------------------------------------------------------

typedef unsigned long long ull;

__device__ __forceinline__ void ffma2(ull& d, ull a, ull b) {
    asm("fma.rn.f32x2 %0, %1, %2, %0;" : "+l"(d) : "l"(a), "l"(b));
}
__device__ __forceinline__ ull dup2(float v) {
    ull r;
    asm("mov.b64 %0, {%1, %1};" : "=l"(r) : "f"(v));
    return r;
}
__device__ __forceinline__ void unpack2(ull v, float& lo, float& hi) {
    asm("mov.b64 {%0, %1}, %2;" : "=f"(lo), "=f"(hi) : "l"(v));
}

__device__ float g_h1[512 * 16 * 32 * 32];   // 33.5 MB
__device__ float g_h2[512 * 32 * 16 * 16];   // 16.8 MB
__device__ float g_h3[512 * 64 * 8 * 8];     //  8.4 MB

// ---------------------------------------------------------------------------
// conv1: in (b,3,64,64) -> fused bn/relu/pool -> (b,16,32,32)
// grid (2,2,512), 256 threads = 16x16 pooled tile. 8 oc-pairs per thread.
// ---------------------------------------------------------------------------
__global__ __launch_bounds__(256) void conv1_kernel(
    const float* __restrict__ x, const float* __restrict__ w,
    const float* __restrict__ cb, const float* __restrict__ bg,
    const float* __restrict__ bb, const float* __restrict__ bm,
    const float* __restrict__ bv)
{
    __shared__ __align__(16) float sp[3][34][34];
    __shared__ __align__(16) float swt[3][9][16];
    __shared__ float ssc[16], ssh[16];

    int b = blockIdx.z, ty = blockIdx.y, tx = blockIdx.x;
    int tid = threadIdx.x;

    // weights (16,3,3,3) -> swt[ic][k][oc]
    for (int i = tid; i < 16 * 27; i += 256) {
        int oc = i / 27, r = i % 27, ic = r / 9, k = r % 9;
        swt[ic][k][oc] = w[i];
    }
    if (tid < 16) {
        float inv = bg[tid] * rsqrtf(bv[tid] + 1e-5f);
        ssc[tid] = inv;
        ssh[tid] = (cb[tid] - bm[tid]) * inv + bb[tid];
    }
    int y0 = ty * 32 - 1, x0 = tx * 32 - 1;
    const float* xb = x + b * 3 * 64 * 64;
    for (int i = tid; i < 3 * 34 * 34; i += 256) {
        int ic = i / 1156, r = i % 1156, yy = r / 34, xx = r % 34;
        int gy = y0 + yy, gx = x0 + xx;
        float val = 0.f;
        if ((unsigned)gy < 64u && (unsigned)gx < 64u)
            val = xb[(ic * 64 + gy) * 64 + gx];
        sp[ic][yy][xx] = val;
    }
    __syncthreads();

    int py = tid >> 4, px = tid & 15;
    int by = 2 * py, bx = 2 * px;

    ull acc[4][8];
#pragma unroll
    for (int p = 0; p < 4; p++)
#pragma unroll
        for (int o = 0; o < 8; o++) acc[p][o] = 0ull;

#pragma unroll 1
    for (int ic = 0; ic < 3; ic++) {
        ull vd[4][4];
#pragma unroll
        for (int a = 0; a < 4; a++)
#pragma unroll
            for (int c = 0; c < 4; c++) vd[a][c] = dup2(sp[ic][by + a][bx + c]);
#pragma unroll
        for (int k = 0; k < 9; k++) {
            const int ky = k / 3, kx = k % 3;
            const ull* wp = (const ull*)swt[ic][k];
#pragma unroll
            for (int o = 0; o < 8; o++) {
                ull wv = wp[o];
                ffma2(acc[0][o], vd[ky][kx], wv);
                ffma2(acc[1][o], vd[ky][kx + 1], wv);
                ffma2(acc[2][o], vd[ky + 1][kx], wv);
                ffma2(acc[3][o], vd[ky + 1][kx + 1], wv);
            }
        }
    }

    int gpy = ty * 16 + py, gpx = tx * 16 + px;
    float* obase = g_h1 + ((size_t)b * 16 * 32 + gpy) * 32 + gpx;
#pragma unroll
    for (int o = 0; o < 8; o++) {
        float a0l, a0h, a1l, a1h, a2l, a2h, a3l, a3h;
        unpack2(acc[0][o], a0l, a0h);
        unpack2(acc[1][o], a1l, a1h);
        unpack2(acc[2][o], a2l, a2h);
        unpack2(acc[3][o], a3l, a3h);
        int oc = 2 * o;
        {
            float sc = ssc[oc], sh = ssh[oc];
            float v0 = fmaxf(a0l * sc + sh, 0.f);
            float v1 = fmaxf(a1l * sc + sh, 0.f);
            float v2 = fmaxf(a2l * sc + sh, 0.f);
            float v3 = fmaxf(a3l * sc + sh, 0.f);
            obase[(size_t)oc * 32 * 32] = fmaxf(fmaxf(v0, v1), fmaxf(v2, v3));
        }
        {
            float sc = ssc[oc + 1], sh = ssh[oc + 1];
            float v0 = fmaxf(a0h * sc + sh, 0.f);
            float v1 = fmaxf(a1h * sc + sh, 0.f);
            float v2 = fmaxf(a2h * sc + sh, 0.f);
            float v3 = fmaxf(a3h * sc + sh, 0.f);
            obase[(size_t)(oc + 1) * 32 * 32] = fmaxf(fmaxf(v0, v1), fmaxf(v2, v3));
        }
    }
}

// ---------------------------------------------------------------------------
// conv2: (b,16,32,32) -> (b,32,16,16). grid (2,2,512), 256 threads:
// 64 pooled pixels (8x8 tile) x 4 oc-groups of 8 channels (4 oc-pairs).
// ---------------------------------------------------------------------------
__global__ __launch_bounds__(256) void conv2_kernel(
    const float* __restrict__ w, const float* __restrict__ cb,
    const float* __restrict__ bg, const float* __restrict__ bb,
    const float* __restrict__ bm, const float* __restrict__ bv)
{
    __shared__ __align__(16) float sp[16][18][18];
    __shared__ __align__(16) float swt[16][9][32];
    __shared__ float ssc[32], ssh[32];

    int b = blockIdx.z, ty = blockIdx.y, tx = blockIdx.x;
    int tid = threadIdx.x;

    for (int i = tid; i < 32 * 144; i += 256) {
        int oc = i / 144, r = i % 144, ic = r / 9, k = r % 9;
        swt[ic][k][oc] = w[i];
    }
    if (tid < 32) {
        float inv = bg[tid] * rsqrtf(bv[tid] + 1e-5f);
        ssc[tid] = inv;
        ssh[tid] = (cb[tid] - bm[tid]) * inv + bb[tid];
    }
    int y0 = ty * 16 - 1, x0 = tx * 16 - 1;
    const float* ib = g_h1 + (size_t)b * 16 * 32 * 32;
    for (int i = tid; i < 16 * 324; i += 256) {
        int ic = i / 324, r = i % 324, yy = r / 18, xx = r % 18;
        int gy = y0 + yy, gx = x0 + xx;
        float val = 0.f;
        if ((unsigned)gy < 32u && (unsigned)gx < 32u)
            val = ib[(ic * 32 + gy) * 32 + gx];
        sp[ic][yy][xx] = val;
    }
    __syncthreads();

    int pix = tid & 63, ocg = tid >> 6;
    int py = pix >> 3, px = pix & 7;
    int by = 2 * py, bx = 2 * px;
    int oc0 = ocg * 8;

    ull acc[4][4];
#pragma unroll
    for (int p = 0; p < 4; p++)
#pragma unroll
        for (int o = 0; o < 4; o++) acc[p][o] = 0ull;

#pragma unroll 1
    for (int ic = 0; ic < 16; ic++) {
        ull vd[4][4];
#pragma unroll
        for (int a = 0; a < 4; a++)
#pragma unroll
            for (int c = 0; c < 4; c++) vd[a][c] = dup2(sp[ic][by + a][bx + c]);
#pragma unroll
        for (int k = 0; k < 9; k++) {
            const int ky = k / 3, kx = k % 3;
            const ull* wp = (const ull*)&swt[ic][k][oc0];
#pragma unroll
            for (int o = 0; o < 4; o++) {
                ull wv = wp[o];
                ffma2(acc[0][o], vd[ky][kx], wv);
                ffma2(acc[1][o], vd[ky][kx + 1], wv);
                ffma2(acc[2][o], vd[ky + 1][kx], wv);
                ffma2(acc[3][o], vd[ky + 1][kx + 1], wv);
            }
        }
    }

    int gpy = ty * 8 + py, gpx = tx * 8 + px;
#pragma unroll
    for (int o = 0; o < 4; o++) {
        float a0l, a0h, a1l, a1h, a2l, a2h, a3l, a3h;
        unpack2(acc[0][o], a0l, a0h);
        unpack2(acc[1][o], a1l, a1h);
        unpack2(acc[2][o], a2l, a2h);
        unpack2(acc[3][o], a3l, a3h);
        int c = oc0 + 2 * o;
        {
            float sc = ssc[c], sh = ssh[c];
            float v0 = fmaxf(a0l * sc + sh, 0.f);
            float v1 = fmaxf(a1l * sc + sh, 0.f);
            float v2 = fmaxf(a2l * sc + sh, 0.f);
            float v3 = fmaxf(a3l * sc + sh, 0.f);
            g_h2[(((size_t)b * 32 + c) * 16 + gpy) * 16 + gpx] =
                fmaxf(fmaxf(v0, v1), fmaxf(v2, v3));
        }
        {
            float sc = ssc[c + 1], sh = ssh[c + 1];
            float v0 = fmaxf(a0h * sc + sh, 0.f);
            float v1 = fmaxf(a1h * sc + sh, 0.f);
            float v2 = fmaxf(a2h * sc + sh, 0.f);
            float v3 = fmaxf(a3h * sc + sh, 0.f);
            g_h2[(((size_t)b * 32 + c + 1) * 16 + gpy) * 16 + gpx] =
                fmaxf(fmaxf(v0, v1), fmaxf(v2, v3));
        }
    }
}

// ---------------------------------------------------------------------------
// conv3: (b,32,16,16) -> (b,64,8,8). One block per image, 512 threads:
// 64 pooled pixels x 8 oc-groups of 8 channels (4 oc-pairs).
// ---------------------------------------------------------------------------
__global__ __launch_bounds__(512) void conv3_kernel(
    const float* __restrict__ w, const float* __restrict__ cb,
    const float* __restrict__ bg, const float* __restrict__ bb,
    const float* __restrict__ bm, const float* __restrict__ bv)
{
    __shared__ __align__(16) float sp[8][18][18];
    __shared__ __align__(16) float swt[8][9][64];
    __shared__ float ssc[64], ssh[64];

    int b = blockIdx.x;
    int tid = threadIdx.x;

    if (tid < 64) {
        float inv = bg[tid] * rsqrtf(bv[tid] + 1e-5f);
        ssc[tid] = inv;
        ssh[tid] = (cb[tid] - bm[tid]) * inv + bb[tid];
    }

    int pix = tid & 63, ocg = tid >> 6;
    int py = pix >> 3, px = pix & 7;
    int by = 2 * py, bx = 2 * px;
    int oc0 = ocg * 8;
    const float* ib = g_h2 + (size_t)b * 32 * 16 * 16;

    ull acc[4][4];
#pragma unroll
    for (int p = 0; p < 4; p++)
#pragma unroll
        for (int o = 0; o < 4; o++) acc[p][o] = 0ull;

#pragma unroll 1
    for (int ch = 0; ch < 4; ch++) {
        __syncthreads();
        for (int i = tid; i < 8 * 324; i += 512) {
            int ic = i / 324, r = i % 324, yy = r / 18, xx = r % 18;
            int gy = yy - 1, gx = xx - 1;
            float val = 0.f;
            if ((unsigned)gy < 16u && (unsigned)gx < 16u)
                val = ib[((ch * 8 + ic) * 16 + gy) * 16 + gx];
            sp[ic][yy][xx] = val;
        }
        // weights (64,32,3,3)
        for (int i = tid; i < 64 * 72; i += 512) {
            int oc = i / 72, r = i % 72, ic = r / 9, k = r % 9;
            swt[ic][k][oc] = w[(oc * 32 + ch * 8 + ic) * 9 + k];
        }
        __syncthreads();

#pragma unroll 1
        for (int ic = 0; ic < 8; ic++) {
            ull vd[4][4];
#pragma unroll
            for (int a = 0; a < 4; a++)
#pragma unroll
                for (int c = 0; c < 4; c++) vd[a][c] = dup2(sp[ic][by + a][bx + c]);
#pragma unroll
            for (int k = 0; k < 9; k++) {
                const int ky = k / 3, kx = k % 3;
                const ull* wp = (const ull*)&swt[ic][k][oc0];
#pragma unroll
                for (int o = 0; o < 4; o++) {
                    ull wv = wp[o];
                    ffma2(acc[0][o], vd[ky][kx], wv);
                    ffma2(acc[1][o], vd[ky][kx + 1], wv);
                    ffma2(acc[2][o], vd[ky + 1][kx], wv);
                    ffma2(acc[3][o], vd[ky + 1][kx + 1], wv);
                }
            }
        }
    }

#pragma unroll
    for (int o = 0; o < 4; o++) {
        float a0l, a0h, a1l, a1h, a2l, a2h, a3l, a3h;
        unpack2(acc[0][o], a0l, a0h);
        unpack2(acc[1][o], a1l, a1h);
        unpack2(acc[2][o], a2l, a2h);
        unpack2(acc[3][o], a3l, a3h);
        int c = oc0 + 2 * o;
        {
            float sc = ssc[c], sh = ssh[c];
            float v0 = fmaxf(a0l * sc + sh, 0.f);
            float v1 = fmaxf(a1l * sc + sh, 0.f);
            float v2 = fmaxf(a2l * sc + sh, 0.f);
            float v3 = fmaxf(a3l * sc + sh, 0.f);
            g_h3[(size_t)b * 4096 + c * 64 + py * 8 + px] =
                fmaxf(fmaxf(v0, v1), fmaxf(v2, v3));
        }
        {
            float sc = ssc[c + 1], sh = ssh[c + 1];
            float v0 = fmaxf(a0h * sc + sh, 0.f);
            float v1 = fmaxf(a1h * sc + sh, 0.f);
            float v2 = fmaxf(a2h * sc + sh, 0.f);
            float v3 = fmaxf(a3h * sc + sh, 0.f);
            g_h3[(size_t)b * 4096 + (c + 1) * 64 + py * 8 + px] =
                fmaxf(fmaxf(v0, v1), fmaxf(v2, v3));
        }
    }
}

// ---------------------------------------------------------------------------
// head: feats (16,256) -> z (16,8) -> theta=0.5*tanh(z) -> analytic quantum
// features (products of cos(theta)) -> classifier (10).
// One block per batch element, 128 threads.
// ---------------------------------------------------------------------------
__global__ __launch_bounds__(128) void head_kernel(
    const float* __restrict__ pw, const float* __restrict__ pb,
    const float* __restrict__ cw, const float* __restrict__ cbias,
    float* __restrict__ out)
{
    __shared__ float sf[4096];
    __shared__ float spart[128 * 8];
    __shared__ float scos[128];
    __shared__ float sfeat[576];
    __shared__ float scpart[10][8];

    int b = blockIdx.x, tid = threadIdx.x;

    const float4* fp4 = (const float4*)(g_h3 + (size_t)b * 4096);
    float4* sf4 = (float4*)sf;
    for (int i = tid; i < 1024; i += 128) sf4[i] = fp4[i];
    __syncthreads();

    {
        int k = tid >> 3, cs = tid & 7;
        float part[8];
#pragma unroll
        for (int d = 0; d < 8; d++) part[d] = 0.f;
        const float* fr = sf + k * 256 + cs * 32;
        const float* wr = pw + k * 2048 + cs * 32 * 8;
#pragma unroll 4
        for (int c = 0; c < 32; c++) {
            float fv = fr[c];
            float4 w0 = ((const float4*)(wr + c * 8))[0];
            float4 w1 = ((const float4*)(wr + c * 8))[1];
            part[0] += fv * w0.x; part[1] += fv * w0.y;
            part[2] += fv * w0.z; part[3] += fv * w0.w;
            part[4] += fv * w1.x; part[5] += fv * w1.y;
            part[6] += fv * w1.z; part[7] += fv * w1.w;
        }
#pragma unroll
        for (int d = 0; d < 8; d++) spart[tid * 8 + d] = part[d];
    }
    __syncthreads();

    {
        int k = tid >> 3, d = tid & 7;
        float z = pb[k * 8 + d];
#pragma unroll
        for (int cs = 0; cs < 8; cs++) z += spart[(k * 8 + cs) * 8 + d];
        scos[tid] = cosf(0.5f * tanhf(z));
    }
    __syncthreads();

    if (tid < 16) {
        const float* c8 = scos + tid * 8;
        float* fo = sfeat + tid * 36;
        float p = 1.f;
#pragma unroll
        for (int q = 0; q < 8; q++) { p *= c8[q]; fo[q] = p; }
        int idx = 8;
#pragma unroll
        for (int i = 0; i < 8; i++) {
#pragma unroll
            for (int j = i + 1; j < 8; j++) {
                float p2 = 1.f;
                for (int m = i + 1; m <= j; m++) p2 *= c8[m];
                fo[idx++] = p2;
            }
        }
    }
    __syncthreads();

    if (tid < 80) {
        int cls = tid >> 3, ch = tid & 7;
        const float* wrow = cw + cls * 576 + ch * 72;
        const float* fr2 = sfeat + ch * 72;
        float s = 0.f;
#pragma unroll 8
        for (int j = 0; j < 72; j++) s += fr2[j] * wrow[j];
        scpart[cls][ch] = s;
    }
    __syncthreads();

    if (tid < 10) {
        float o = cbias[tid];
#pragma unroll
        for (int ch = 0; ch < 8; ch++) o += scpart[tid][ch];
        out[b * 10 + tid] = o;
    }
}

// ---------------------------------------------------------------------------
extern "C" void kernel_launch(void* const* d_in, const int* in_sizes, int n_in,
                              void* d_out, int out_size)
{
    const float* x    = (const float*)d_in[0];
    const float* c1w  = (const float*)d_in[1];
    const float* c1b  = (const float*)d_in[2];
    const float* g1   = (const float*)d_in[3];
    const float* b1   = (const float*)d_in[4];
    const float* m1   = (const float*)d_in[5];
    const float* v1   = (const float*)d_in[6];
    const float* c2w  = (const float*)d_in[7];
    const float* c2b  = (const float*)d_in[8];
    const float* g2   = (const float*)d_in[9];
    const float* b2   = (const float*)d_in[10];
    const float* m2   = (const float*)d_in[11];
    const float* v2   = (const float*)d_in[12];
    const float* c3w  = (const float*)d_in[13];
    const float* c3b  = (const float*)d_in[14];
    const float* g3   = (const float*)d_in[15];
    const float* b3   = (const float*)d_in[16];
    const float* m3   = (const float*)d_in[17];
    const float* v3   = (const float*)d_in[18];
    const float* pw   = (const float*)d_in[19];
    const float* pb   = (const float*)d_in[20];
    const float* cw   = (const float*)d_in[21];
    const float* cb   = (const float*)d_in[22];
    float* out = (float*)d_out;

    conv1_kernel<<<dim3(2, 2, 512), 256>>>(x, c1w, c1b, g1, b1, m1, v1);
    conv2_kernel<<<dim3(2, 2, 512), 256>>>(c2w, c2b, g2, b2, m2, v2);
    conv3_kernel<<<512, 512>>>(c3w, c3b, g3, b3, m3, v3);
    head_kernel<<<512, 128>>>(pw, pb, cw, cb, out);
}